// round 11
// baseline (speedup 1.0000x reference)
#include <cuda_runtime.h>
#include <cuda_bf16.h>
#include <cstdint>
#include <math.h>

#define E_DIM   1024
#define NH      16
#define DH      64
#define BATCH   2
#define TSEQ    2048
#define MROWS   (BATCH * TSEQ)   // 4096

typedef __nv_bfloat16 bf16;

// Scratch (allocation-free rule: use __device__ globals)
__device__ bf16 g_xqhi[MROWS * E_DIM];  // also attn output
__device__ bf16 g_xqlo[MROWS * E_DIM];
__device__ bf16 g_xkhi[MROWS * E_DIM];
__device__ bf16 g_xklo[MROWS * E_DIM];
__device__ bf16 g_xvhi[MROWS * E_DIM];
__device__ bf16 g_xvlo[MROWS * E_DIM];
__device__ bf16 g_wqhi[E_DIM * E_DIM];
__device__ bf16 g_wqlo[E_DIM * E_DIM];
__device__ bf16 g_wkhi[E_DIM * E_DIM];
__device__ bf16 g_wklo[E_DIM * E_DIM];
__device__ bf16 g_wvhi[E_DIM * E_DIM];
__device__ bf16 g_wvlo[E_DIM * E_DIM];
__device__ bf16 g_wohi[E_DIM * E_DIM];
__device__ bf16 g_wolo[E_DIM * E_DIM];
__device__ bf16 g_Qhi[MROWS * E_DIM];
__device__ bf16 g_Qlo[MROWS * E_DIM];
__device__ bf16 g_Khi[MROWS * E_DIM];
__device__ bf16 g_Klo[MROWS * E_DIM];
__device__ bf16 g_Vhi[MROWS * E_DIM];
__device__ bf16 g_Vlo[MROWS * E_DIM];

// ---------------------------------------------------------------------------
// Helpers
// ---------------------------------------------------------------------------
__device__ __forceinline__ uint32_t smem_u32(const void* p) {
    uint32_t a;
    asm("{ .reg .u64 t; cvta.to.shared.u64 t, %1; cvt.u32.u64 %0, t; }"
        : "=r"(a) : "l"(p));
    return a;
}

#define SW128(off) ((off) ^ (((off) >> 3) & 0x70))
#define SW64(off)  ((off) ^ (((off) >> 3) & 0x30))

__device__ __forceinline__ void cp_async16(uint32_t dst, const void* src) {
    asm volatile("cp.async.cg.shared.global [%0], [%1], 16;"
                 :: "r"(dst), "l"(src) : "memory");
}
#define CP_COMMIT() asm volatile("cp.async.commit_group;" ::: "memory")
#define CP_WAIT(n)  asm volatile("cp.async.wait_group %0;" :: "n"(n) : "memory")

__device__ __forceinline__ void ldsm_x4(uint32_t& r0, uint32_t& r1,
                                        uint32_t& r2, uint32_t& r3, uint32_t addr) {
    asm volatile("ldmatrix.sync.aligned.m8n8.x4.shared.b16 {%0,%1,%2,%3}, [%4];"
                 : "=r"(r0), "=r"(r1), "=r"(r2), "=r"(r3) : "r"(addr));
}
__device__ __forceinline__ void ldsm_x4t(uint32_t& r0, uint32_t& r1,
                                         uint32_t& r2, uint32_t& r3, uint32_t addr) {
    asm volatile("ldmatrix.sync.aligned.m8n8.x4.trans.shared.b16 {%0,%1,%2,%3}, [%4];"
                 : "=r"(r0), "=r"(r1), "=r"(r2), "=r"(r3) : "r"(addr));
}
__device__ __forceinline__ void ldsm_x2(uint32_t& r0, uint32_t& r1, uint32_t addr) {
    asm volatile("ldmatrix.sync.aligned.m8n8.x2.shared.b16 {%0,%1}, [%2];"
                 : "=r"(r0), "=r"(r1) : "r"(addr));
}
__device__ __forceinline__ void mma_bf16(float* c, const uint32_t* a, const uint32_t* b) {
    asm volatile(
        "mma.sync.aligned.m16n8k16.row.col.f32.bf16.bf16.f32 "
        "{%0,%1,%2,%3}, {%4,%5,%6,%7}, {%8,%9}, {%0,%1,%2,%3};"
        : "+f"(c[0]), "+f"(c[1]), "+f"(c[2]), "+f"(c[3])
        : "r"(a[0]), "r"(a[1]), "r"(a[2]), "r"(a[3]), "r"(b[0]), "r"(b[1]));
}
__device__ __forceinline__ uint32_t pk_bf16x2(float lo, float hi) {
    uint32_t r;
    asm("cvt.rn.bf16x2.f32 %0, %1, %2;" : "=r"(r) : "f"(hi), "f"(lo));
    return r;
}
__device__ __forceinline__ float bf16rt(float x) {
    return __bfloat162float(__float2bfloat16(x));
}

// ---------------------------------------------------------------------------
// Fused split: up to 4 tensors, selected by blockIdx.y
// ---------------------------------------------------------------------------
struct SplitArgs {
    const float* x[4];
    bf16* hi[4];
    bf16* lo[4];
};

__global__ __launch_bounds__(256) void split_many_kernel(SplitArgs args, int n)
{
    const int s = blockIdx.y;
    const float* x = args.x[s];
    bf16* hi = args.hi[s];
    bf16* lo = args.lo[s];
    int i = (blockIdx.x * 256 + threadIdx.x) * 4;
    if (i >= n) return;
    float4 v = *(const float4*)&x[i];
    bf16 h0 = __float2bfloat16(v.x);
    bf16 h1 = __float2bfloat16(v.y);
    bf16 h2 = __float2bfloat16(v.z);
    bf16 h3 = __float2bfloat16(v.w);
    bf16 l0 = __float2bfloat16(v.x - __bfloat162float(h0));
    bf16 l1 = __float2bfloat16(v.y - __bfloat162float(h1));
    bf16 l2 = __float2bfloat16(v.z - __bfloat162float(h2));
    bf16 l3 = __float2bfloat16(v.w - __bfloat162float(h3));
    ((__nv_bfloat162*)&hi[i])[0] = __nv_bfloat162(h0, h1);
    ((__nv_bfloat162*)&hi[i])[1] = __nv_bfloat162(h2, h3);
    ((__nv_bfloat162*)&lo[i])[0] = __nv_bfloat162(l0, l1);
    ((__nv_bfloat162*)&lo[i])[1] = __nv_bfloat162(l2, l3);
}

// ---------------------------------------------------------------------------
// HMMA GEMM (NT): C = (Ahi+Alo) * (Bhi+Blo)^T, 128x128 CTA tile, BK=32.
// cp.async double-buffered (2 x 32KB smem, SW64 rows) -> 2 CTAs/SM.
// blockIdx.z selects problem (batched QKV). write_bf16 flag selects output.
// ---------------------------------------------------------------------------
#define GK        1024
#define GN        1024
#define BKC       32
#define NCHUNKS   (GK / BKC)        // 32
#define TILE32_B  (128 * 64)        // 8 KB per bf16 tile (128 rows x 64B)
#define GSM_AHI   0
#define GSM_ALO   (TILE32_B)
#define GSM_BHI   (2 * TILE32_B)
#define GSM_BLO   (3 * TILE32_B)
#define GBUF_B    (4 * TILE32_B)    // 32 KB per buffer
#define GSM_TOTAL (2 * GBUF_B)      // 64 KB

struct GemmArgs {
    const bf16* Ah[3];
    const bf16* Al[3];
    const bf16* Bh[3];
    const bf16* Bl[3];
    float* Cf[3];
    bf16* Ch[3];
    bf16* Cl[3];
    int write_bf16;
};

__global__ __launch_bounds__(256, 2) void mma_gemm_nt(GemmArgs args)
{
    extern __shared__ __align__(1024) char smem[];
    const uint32_t sbase = smem_u32(smem);
    const int z      = blockIdx.z;
    const int tid    = threadIdx.x;
    const int wid    = tid >> 5;
    const int lane   = tid & 31;
    const int warp_m = wid >> 2;
    const int warp_n = wid & 3;
    const int row0   = blockIdx.y * 128;
    const int col0   = blockIdx.x * 128;

    float acc[4][4][4];
#pragma unroll
    for (int i = 0; i < 4; i++)
#pragma unroll
        for (int j = 0; j < 4; j++)
#pragma unroll
            for (int r = 0; r < 4; r++) acc[i][j][r] = 0.f;

    const bf16* srcA[2] = { args.Ah[z] + (size_t)row0 * GK, args.Al[z] + (size_t)row0 * GK };
    const bf16* srcB[2] = { args.Bh[z] + (size_t)col0 * GK, args.Bl[z] + (size_t)col0 * GK };
    const uint32_t tileOff[4] = { GSM_AHI, GSM_ALO, GSM_BHI, GSM_BLO };

    uint32_t a_row[4], b_row[4];
#pragma unroll
    for (int mf = 0; mf < 4; mf++)
        a_row[mf] = (uint32_t)(warp_m * 64 + mf * 16 + (lane & 15)) * 64;
#pragma unroll
    for (int nf = 0; nf < 4; nf++)
        b_row[nf] = (uint32_t)(warp_n * 32 + nf * 8 + (lane & 7)) * 64;
    const uint32_t a_col = (uint32_t)(lane >> 4) * 16;
    const uint32_t b_col = (uint32_t)((lane >> 3) & 1) * 16;

    // async load of k-chunk c into buffer buf (2048 granules, 8 per thread)
    auto load_chunk = [&](int c, int buf) {
        const uint32_t bb = sbase + buf * GBUF_B;
#pragma unroll
        for (int i = tid; i < 2048; i += 256) {
            int t   = i >> 9;
            int idx = i & 511;
            int r   = idx >> 2;
            int g   = idx & 3;
            const bf16* src =
                (t < 2 ? srcA[t] : srcB[t - 2]) + (size_t)r * GK + c * BKC + g * 8;
            uint32_t off = (uint32_t)(r * 64 + g * 16);
            cp_async16(bb + tileOff[t] + SW64(off), src);
        }
        CP_COMMIT();
    };

    load_chunk(0, 0);

    for (int c = 0; c < NCHUNKS; c++) {
        if (c + 1 < NCHUNKS) {
            load_chunk(c + 1, (c + 1) & 1);
            CP_WAIT(1);
        } else {
            CP_WAIT(0);
        }
        __syncthreads();

        const uint32_t bb = sbase + (c & 1) * GBUF_B;
#pragma unroll
        for (int ks = 0; ks < 2; ks++) {
            const uint32_t kb = ks * 32;
            uint32_t ah[4][4], bh[4][2], bl[4][2];
#pragma unroll
            for (int mf = 0; mf < 4; mf++) {
                uint32_t off = SW64(a_row[mf] + kb + a_col);
                ldsm_x4(ah[mf][0], ah[mf][1], ah[mf][2], ah[mf][3], bb + GSM_AHI + off);
            }
#pragma unroll
            for (int nf = 0; nf < 4; nf++) {
                uint32_t off = SW64(b_row[nf] + kb + b_col);
                ldsm_x2(bh[nf][0], bh[nf][1], bb + GSM_BHI + off);
                ldsm_x2(bl[nf][0], bl[nf][1], bb + GSM_BLO + off);
            }
            // hi*hi and hi*lo first (ah dies before al loads -> lower reg peak)
#pragma unroll
            for (int mf = 0; mf < 4; mf++)
#pragma unroll
                for (int nf = 0; nf < 4; nf++) {
                    mma_bf16(acc[mf][nf], ah[mf], bh[nf]);
                    mma_bf16(acc[mf][nf], ah[mf], bl[nf]);
                }
            uint32_t al[4][4];
#pragma unroll
            for (int mf = 0; mf < 4; mf++) {
                uint32_t off = SW64(a_row[mf] + kb + a_col);
                ldsm_x4(al[mf][0], al[mf][1], al[mf][2], al[mf][3], bb + GSM_ALO + off);
            }
#pragma unroll
            for (int mf = 0; mf < 4; mf++)
#pragma unroll
                for (int nf = 0; nf < 4; nf++)
                    mma_bf16(acc[mf][nf], al[mf], bh[nf]);
        }
        __syncthreads();
    }

    const int rbase = row0 + warp_m * 64 + (lane >> 2);
    const int cbase = col0 + warp_n * 32 + 2 * (lane & 3);
    if (!args.write_bf16) {
        float* C = args.Cf[z];
#pragma unroll
        for (int mf = 0; mf < 4; mf++)
#pragma unroll
            for (int nf = 0; nf < 4; nf++) {
                float* p0 = &C[(size_t)(rbase + mf * 16) * GN + cbase + nf * 8];
                float* p1 = &C[(size_t)(rbase + mf * 16 + 8) * GN + cbase + nf * 8];
                *(float2*)p0 = make_float2(acc[mf][nf][0], acc[mf][nf][1]);
                *(float2*)p1 = make_float2(acc[mf][nf][2], acc[mf][nf][3]);
            }
    } else {
        bf16* Chi = args.Ch[z];
        bf16* Clo = args.Cl[z];
#pragma unroll
        for (int mf = 0; mf < 4; mf++)
#pragma unroll
            for (int nf = 0; nf < 4; nf++) {
                size_t o0 = (size_t)(rbase + mf * 16) * GN + cbase + nf * 8;
                size_t o1 = (size_t)(rbase + mf * 16 + 8) * GN + cbase + nf * 8;
                float x0 = acc[mf][nf][0], x1 = acc[mf][nf][1];
                float x2 = acc[mf][nf][2], x3 = acc[mf][nf][3];
                float h0 = bf16rt(x0), h1 = bf16rt(x1);
                float h2 = bf16rt(x2), h3 = bf16rt(x3);
                *(uint32_t*)&Chi[o0] = pk_bf16x2(h0, h1);
                *(uint32_t*)&Chi[o1] = pk_bf16x2(h2, h3);
                *(uint32_t*)&Clo[o0] = pk_bf16x2(x0 - h0, x1 - h1);
                *(uint32_t*)&Clo[o1] = pk_bf16x2(x2 - h2, x3 - h3);
            }
    }
}

// ---------------------------------------------------------------------------
// HMMA causal flash attention, cp.async double-buffered KV.
// Q smem region is reused as KV buffer 0 after fragment extraction -> 64KB.
// Largest-work q-tiles launch first (reversed blockIdx.x).
// ---------------------------------------------------------------------------
#define AQ_HI 0
#define AQ_LO 16384
#define KV_B  32768          // per-buffer: Khi 8K, Klo 8K, Vhi 8K, Vlo 8K
#define ASM_TOTAL (2 * KV_B) // 64 KB

__global__ __launch_bounds__(256, 1) void attn_mma_kernel(
    const bf16* __restrict__ Qhi, const bf16* __restrict__ Qlo,
    const bf16* __restrict__ Khi, const bf16* __restrict__ Klo,
    const bf16* __restrict__ Vhi, const bf16* __restrict__ Vlo,
    bf16* __restrict__ Ohi, bf16* __restrict__ Olo)
{
    extern __shared__ __align__(1024) char smem[];
    const uint32_t sbase = smem_u32(smem);
    const int b    = blockIdx.z;
    const int h    = blockIdx.y;
    const int qt   = (int)gridDim.x - 1 - (int)blockIdx.x;  // biggest work first
    const int q0   = qt * 128;
    const int tid  = threadIdx.x;
    const int wid  = tid >> 5;
    const int lane = tid & 31;

    const int nfull  = q0 / 64;
    const int ntiles = nfull + 2;

    // KV tile t lives in buffer ((t&1)^1): tile0 -> upper half (clear of Q)
    auto load_kv = [&](int t) {
        const int k0 = t * 64;
        const uint32_t bb = sbase + ((t & 1) ^ 1) * KV_B;
#pragma unroll
        for (int i = tid; i < 2048; i += 256) {
            int arr = i >> 9;          // 0:Khi 1:Klo 2:Vhi 3:Vlo
            int idx = i & 511;
            int r   = idx >> 3;
            int g   = idx & 7;
            const bf16* src =
                (arr == 0 ? Khi : arr == 1 ? Klo : arr == 2 ? Vhi : Vlo)
                + (size_t)(b * TSEQ + k0 + r) * E_DIM + h * DH + g * 8;
            uint32_t off = (uint32_t)(r * 128 + g * 16);
            cp_async16(bb + arr * 8192 + SW128(off), src);
        }
        CP_COMMIT();
    };

    load_kv(0);    // into upper 32KB; overlaps the Q fill below

    // --- Q fill into lower 32KB ---
#pragma unroll
    for (int i = tid; i < 2048; i += 256) {
        int arr = i >> 10;
        int idx = i & 1023;
        int r   = idx >> 3;
        int g   = idx & 7;
        const bf16* src =
            (arr ? Qlo : Qhi) + (size_t)(b * TSEQ + q0 + r) * E_DIM + h * DH + g * 8;
        float4 v = *(const float4*)src;
        uint32_t off = (uint32_t)(r * 128 + g * 16);
        *(float4*)(smem + (arr ? AQ_LO : AQ_HI) + SW128(off)) = v;
    }
    __syncthreads();

    // --- Q fragments ---
    uint32_t qh[4][4], ql[4][4];
#pragma unroll
    for (int j = 0; j < 4; j++) {
        uint32_t off = SW128((uint32_t)(wid * 16 + (lane & 15)) * 128
                             + j * 32 + (lane >> 4) * 16);
        ldsm_x4(qh[j][0], qh[j][1], qh[j][2], qh[j][3], sbase + AQ_HI + off);
        ldsm_x4(ql[j][0], ql[j][1], ql[j][2], ql[j][3], sbase + AQ_LO + off);
    }
    __syncthreads();   // Q region free for KV buffer reuse only after this

    float o[8][4];
#pragma unroll
    for (int i = 0; i < 8; i++)
#pragma unroll
        for (int r = 0; r < 4; r++) o[i][r] = 0.f;
    float m0 = -INFINITY, m1 = -INFINITY, l0 = 0.f, l1 = 0.f;

    for (int t = 0; t < ntiles; t++) {
        if (t + 1 < ntiles) {
            load_kv(t + 1);
            CP_WAIT(1);
        } else {
            CP_WAIT(0);
        }
        __syncthreads();

        const uint32_t bb = sbase + ((t & 1) ^ 1) * KV_B;
        const int k0 = t * 64;

        // --- S = Q K^T (3 combos) ---
        float s[8][4];
#pragma unroll
        for (int i = 0; i < 8; i++)
#pragma unroll
            for (int r = 0; r < 4; r++) s[i][r] = 0.f;

#pragma unroll
        for (int ks = 0; ks < 4; ks++) {
            uint32_t bh[8][2], bl[8][2];
#pragma unroll
            for (int nb = 0; nb < 4; nb++) {
                uint32_t off = SW128((uint32_t)(nb * 16 + ((lane >> 4) << 3) + (lane & 7)) * 128
                                     + ks * 32 + ((lane >> 3) & 1) * 16);
                ldsm_x4(bh[2 * nb][0], bh[2 * nb][1], bh[2 * nb + 1][0], bh[2 * nb + 1][1],
                        bb + 0 + off);
                ldsm_x4(bl[2 * nb][0], bl[2 * nb][1], bl[2 * nb + 1][0], bl[2 * nb + 1][1],
                        bb + 8192 + off);
            }
#pragma unroll
            for (int nf = 0; nf < 8; nf++) {
                mma_bf16(s[nf], qh[ks], bh[nf]);
                mma_bf16(s[nf], qh[ks], bl[nf]);
                mma_bf16(s[nf], ql[ks], bh[nf]);
            }
        }
        // apply 1/sqrt(DH) = 0.125
#pragma unroll
        for (int nf = 0; nf < 8; nf++)
#pragma unroll
            for (int r = 0; r < 4; r++) s[nf][r] *= 0.125f;

        // --- causal mask ---
        if (t >= nfull) {
            const int r0g = q0 + wid * 16 + (lane >> 2);
            const int r1g = r0g + 8;
            const int cb  = k0 + 2 * (lane & 3);
#pragma unroll
            for (int nf = 0; nf < 8; nf++) {
                int c0 = cb + nf * 8, c1 = c0 + 1;
                if (c0 > r0g) s[nf][0] = -INFINITY;
                if (c1 > r0g) s[nf][1] = -INFINITY;
                if (c0 > r1g) s[nf][2] = -INFINITY;
                if (c1 > r1g) s[nf][3] = -INFINITY;
            }
        }

        // --- online softmax ---
        float rm0 = s[0][0], rm1 = s[0][2];
#pragma unroll
        for (int nf = 0; nf < 8; nf++) {
            rm0 = fmaxf(rm0, fmaxf(s[nf][0], s[nf][1]));
            rm1 = fmaxf(rm1, fmaxf(s[nf][2], s[nf][3]));
        }
        rm0 = fmaxf(rm0, __shfl_xor_sync(0xFFFFFFFFu, rm0, 1));
        rm0 = fmaxf(rm0, __shfl_xor_sync(0xFFFFFFFFu, rm0, 2));
        rm1 = fmaxf(rm1, __shfl_xor_sync(0xFFFFFFFFu, rm1, 1));
        rm1 = fmaxf(rm1, __shfl_xor_sync(0xFFFFFFFFu, rm1, 2));
        float mn0 = fmaxf(m0, rm0), mn1 = fmaxf(m1, rm1);
        float cr0 = __expf(m0 - mn0), cr1 = __expf(m1 - mn1);
        m0 = mn0; m1 = mn1;
        l0 *= cr0; l1 *= cr1;
#pragma unroll
        for (int nf = 0; nf < 8; nf++) {
            o[nf][0] *= cr0; o[nf][1] *= cr0;
            o[nf][2] *= cr1; o[nf][3] *= cr1;
        }

        uint32_t uhi[8], ulo[8], vhi2[8], vlo2[8];
#pragma unroll
        for (int nf = 0; nf < 8; nf++) {
            float p0 = __expf(s[nf][0] - mn0);
            float p1 = __expf(s[nf][1] - mn0);
            float p2 = __expf(s[nf][2] - mn1);
            float p3 = __expf(s[nf][3] - mn1);
            l0 += p0 + p1; l1 += p2 + p3;
            float h0 = bf16rt(p0), h1 = bf16rt(p1);
            float h2 = bf16rt(p2), h3 = bf16rt(p3);
            uhi[nf]  = pk_bf16x2(h0, h1);
            vhi2[nf] = pk_bf16x2(h2, h3);
            ulo[nf]  = pk_bf16x2(p0 - h0, p1 - h1);
            vlo2[nf] = pk_bf16x2(p2 - h2, p3 - h3);
        }

        // --- O += P V (3 combos) ---
#pragma unroll
        for (int j = 0; j < 4; j++) {
            uint32_t pah[4] = { uhi[2 * j], vhi2[2 * j], uhi[2 * j + 1], vhi2[2 * j + 1] };
            uint32_t pal[4] = { ulo[2 * j], vlo2[2 * j], ulo[2 * j + 1], vlo2[2 * j + 1] };
            uint32_t vh[8][2], vl[8][2];
#pragma unroll
            for (int db = 0; db < 4; db++) {
                uint32_t off = SW128((uint32_t)(j * 16 + (lane & 15)) * 128
                                     + (db * 16 + ((lane >> 4) << 3)) * 2);
                ldsm_x4t(vh[2 * db][0], vh[2 * db][1], vh[2 * db + 1][0], vh[2 * db + 1][1],
                         bb + 16384 + off);
                ldsm_x4t(vl[2 * db][0], vl[2 * db][1], vl[2 * db + 1][0], vl[2 * db + 1][1],
                         bb + 24576 + off);
            }
#pragma unroll
            for (int nd = 0; nd < 8; nd++) {
                mma_bf16(o[nd], pah, vh[nd]);
                mma_bf16(o[nd], pah, vl[nd]);
                mma_bf16(o[nd], pal, vh[nd]);
            }
        }
        __syncthreads();
    }

    // --- finalize ---
    l0 += __shfl_xor_sync(0xFFFFFFFFu, l0, 1);
    l0 += __shfl_xor_sync(0xFFFFFFFFu, l0, 2);
    l1 += __shfl_xor_sync(0xFFFFFFFFu, l1, 1);
    l1 += __shfl_xor_sync(0xFFFFFFFFu, l1, 2);
    const float inv0 = 1.f / l0, inv1 = 1.f / l1;
    const size_t gr0 = (size_t)(b * TSEQ + q0 + wid * 16 + (lane >> 2)) * E_DIM;
    const size_t gr1 = gr0 + 8 * E_DIM;
    const int cb = h * DH + 2 * (lane & 3);
#pragma unroll
    for (int nd = 0; nd < 8; nd++) {
        float x0 = o[nd][0] * inv0, x1 = o[nd][1] * inv0;
        float x2 = o[nd][2] * inv1, x3 = o[nd][3] * inv1;
        float h0 = bf16rt(x0), h1 = bf16rt(x1);
        float h2 = bf16rt(x2), h3 = bf16rt(x3);
        size_t c0 = gr0 + cb + nd * 8;
        size_t c1 = gr1 + cb + nd * 8;
        *(uint32_t*)&Ohi[c0] = pk_bf16x2(h0, h1);
        *(uint32_t*)&Ohi[c1] = pk_bf16x2(h2, h3);
        *(uint32_t*)&Olo[c0] = pk_bf16x2(x0 - h0, x1 - h1);
        *(uint32_t*)&Olo[c1] = pk_bf16x2(x2 - h2, x3 - h3);
    }
}

// ---------------------------------------------------------------------------
// Launch
// ---------------------------------------------------------------------------
extern "C" void kernel_launch(void* const* d_in, const int* in_sizes, int n_in,
                              void* d_out, int out_size)
{
    const float* q  = (const float*)d_in[0];
    const float* k  = (const float*)d_in[1];
    const float* v  = (const float*)d_in[2];
    const float* Wq = (const float*)d_in[3];
    const float* Wk = (const float*)d_in[4];
    const float* Wv = (const float*)d_in[5];
    const float* Wo = (const float*)d_in[6];
    float* out = (float*)d_out;

    bf16 *xqhi, *xqlo, *xkhi, *xklo, *xvhi, *xvlo;
    bf16 *wqhi, *wqlo, *wkhi, *wklo, *wvhi, *wvlo, *wohi, *wolo;
    bf16 *Qhi, *Qlo, *Khi, *Klo, *Vhi, *Vlo;
    cudaGetSymbolAddress((void**)&xqhi, g_xqhi);
    cudaGetSymbolAddress((void**)&xqlo, g_xqlo);
    cudaGetSymbolAddress((void**)&xkhi, g_xkhi);
    cudaGetSymbolAddress((void**)&xklo, g_xklo);
    cudaGetSymbolAddress((void**)&xvhi, g_xvhi);
    cudaGetSymbolAddress((void**)&xvlo, g_xvlo);
    cudaGetSymbolAddress((void**)&wqhi, g_wqhi);
    cudaGetSymbolAddress((void**)&wqlo, g_wqlo);
    cudaGetSymbolAddress((void**)&wkhi, g_wkhi);
    cudaGetSymbolAddress((void**)&wklo, g_wklo);
    cudaGetSymbolAddress((void**)&wvhi, g_wvhi);
    cudaGetSymbolAddress((void**)&wvlo, g_wvlo);
    cudaGetSymbolAddress((void**)&wohi, g_wohi);
    cudaGetSymbolAddress((void**)&wolo, g_wolo);
    cudaGetSymbolAddress((void**)&Qhi, g_Qhi);
    cudaGetSymbolAddress((void**)&Qlo, g_Qlo);
    cudaGetSymbolAddress((void**)&Khi, g_Khi);
    cudaGetSymbolAddress((void**)&Klo, g_Klo);
    cudaGetSymbolAddress((void**)&Vhi, g_Vhi);
    cudaGetSymbolAddress((void**)&Vlo, g_Vlo);

    cudaFuncSetAttribute(mma_gemm_nt,
                         cudaFuncAttributeMaxDynamicSharedMemorySize, GSM_TOTAL);
    cudaFuncSetAttribute(attn_mma_kernel,
                         cudaFuncAttributeMaxDynamicSharedMemorySize, ASM_TOTAL);

    const int NX = MROWS * E_DIM;
    const int NW = E_DIM * E_DIM;

    // Split q, k, v (one launch)
    SplitArgs sx;
    sx.x[0] = q;  sx.hi[0] = xqhi; sx.lo[0] = xqlo;
    sx.x[1] = k;  sx.hi[1] = xkhi; sx.lo[1] = xklo;
    sx.x[2] = v;  sx.hi[2] = xvhi; sx.lo[2] = xvlo;
    sx.x[3] = q;  sx.hi[3] = xqhi; sx.lo[3] = xqlo;  // unused
    split_many_kernel<<<dim3(NX / 1024, 3), 256>>>(sx, NX);

    // Split 4 weights (one launch)
    SplitArgs sw;
    sw.x[0] = Wq; sw.hi[0] = wqhi; sw.lo[0] = wqlo;
    sw.x[1] = Wk; sw.hi[1] = wkhi; sw.lo[1] = wklo;
    sw.x[2] = Wv; sw.hi[2] = wvhi; sw.lo[2] = wvlo;
    sw.x[3] = Wo; sw.hi[3] = wohi; sw.lo[3] = wolo;
    split_many_kernel<<<dim3(NW / 1024, 4), 256>>>(sw, NW);

    // Batched QKV projection (one launch, grid.z = 3)
    GemmArgs gq;
    gq.Ah[0] = xqhi; gq.Al[0] = xqlo; gq.Bh[0] = wqhi; gq.Bl[0] = wqlo;
    gq.Ah[1] = xkhi; gq.Al[1] = xklo; gq.Bh[1] = wkhi; gq.Bl[1] = wklo;
    gq.Ah[2] = xvhi; gq.Al[2] = xvlo; gq.Bh[2] = wvhi; gq.Bl[2] = wvlo;
    gq.Cf[0] = gq.Cf[1] = gq.Cf[2] = nullptr;
    gq.Ch[0] = Qhi; gq.Cl[0] = Qlo;
    gq.Ch[1] = Khi; gq.Cl[1] = Klo;
    gq.Ch[2] = Vhi; gq.Cl[2] = Vlo;
    gq.write_bf16 = 1;
    mma_gemm_nt<<<dim3(GN / 128, MROWS / 128, 3), 256, GSM_TOTAL>>>(gq);

    // Attention: writes bf16 hi/lo into xq buffers (free after QKV GEMM)
    attn_mma_kernel<<<dim3(TSEQ / 128, NH, BATCH), 256, ASM_TOTAL>>>(
        Qhi, Qlo, Khi, Klo, Vhi, Vlo, xqhi, xqlo);

    // Output projection -> fp32
    GemmArgs go;
    go.Ah[0] = xqhi; go.Al[0] = xqlo; go.Bh[0] = wohi; go.Bl[0] = wolo;
    go.Ah[1] = go.Ah[2] = xqhi; go.Al[1] = go.Al[2] = xqlo;
    go.Bh[1] = go.Bh[2] = wohi; go.Bl[1] = go.Bl[2] = wolo;
    go.Cf[0] = go.Cf[1] = go.Cf[2] = out;
    go.Ch[0] = go.Ch[1] = go.Ch[2] = nullptr;
    go.Cl[0] = go.Cl[1] = go.Cl[2] = nullptr;
    go.write_bf16 = 0;
    mma_gemm_nt<<<dim3(GN / 128, MROWS / 128, 1), 256, GSM_TOTAL>>>(go);
}